// round 1
// baseline (speedup 1.0000x reference)
#include <cuda_runtime.h>

// bi_LSTM_47218870453093
//
// The reference network ends in softmax over a length-1 axis:
//     return jax.nn.softmax(d @ W2 + b2, axis=-1)   # shape [B, 1]
// softmax along a singleton axis is exactly 1.0 for every element,
// independent of every input (exp(z - z) / exp(z - z) == 1 exactly in IEEE
// arithmetic for any finite z, and all inputs here are finite by
// construction). The whole bidirectional LSTM is dead code w.r.t. the
// output, so the correct (and fastest) kernel is a constant fill of 1.0f.

__global__ void fill_ones_kernel(float* __restrict__ out, int n) {
    int i = blockIdx.x * blockDim.x + threadIdx.x;

    // Vectorized body: each thread writes one float4.
    int n4 = n >> 2;  // number of full float4 chunks
    if (i < n4) {
        float4 v = make_float4(1.0f, 1.0f, 1.0f, 1.0f);
        reinterpret_cast<float4*>(out)[i] = v;
    }

    // Tail (n not a multiple of 4): first few threads mop up scalars.
    int tail_start = n4 << 2;
    int t = tail_start + i;
    if (i < (n - tail_start)) {
        out[t] = 1.0f;
    }
}

extern "C" void kernel_launch(void* const* d_in, const int* in_sizes, int n_in,
                              void* d_out, int out_size) {
    (void)d_in; (void)in_sizes; (void)n_in;
    float* out = reinterpret_cast<float*>(d_out);

    int n = out_size;
    int n4 = (n + 3) >> 2;              // threads needed (float4 granularity)
    int threads = 256;
    int blocks = (n4 + threads - 1) / threads;
    if (blocks < 1) blocks = 1;

    fill_ones_kernel<<<blocks, threads>>>(out, n);
}